// round 1
// baseline (speedup 1.0000x reference)
#include <cuda_runtime.h>
#include <cstdint>

#define HH 19
#define CELLS 361
#define MASK19 0x7FFFFu
#define BPB 32                 // boards per block
#define NTHREADS (BPB * HH)    // 608 = 19 warps exactly

__global__ __launch_bounds__(NTHREADS)
void go_feat_kernel(const float* __restrict__ stones,
                    const int*   __restrict__ cur_player,
                    const int*   __restrict__ ko_points,
                    float*       __restrict__ out,
                    int B)
{
    // Per-board row bitmasks, 21 rows each (rows 0 and 20 are zero padding,
    // real rows live at [1..19]). Bits 0..18 = columns, bits 19..31 = 0.
    __shared__ uint32_t m_cur [BPB][21];
    __shared__ uint32_t m_opp [BPB][21];
    __shared__ uint32_t m_emp [BPB][21];
    __shared__ uint32_t m_weak[BPB][21];

    const int t  = threadIdx.x;
    const int lb = t / HH;       // local board within block
    const int r  = t % HH;       // row 0..18
    int b = blockIdx.x * BPB + lb;
    const bool active = (b < B);
    if (!active) b = 0;          // keep all threads alive for __syncthreads

    // ---------- Phase 1: pack input rows into bitmasks ----------
    const int cpv = cur_player[b];
    const float* s0 = stones + (size_t)b * (2 * CELLS) + r * HH;
    const float* s1 = s0 + CELLS;

    uint32_t bits0 = 0u, bits1 = 0u;
#pragma unroll
    for (int c = 0; c < HH; ++c) {
        if (s0[c] > 0.5f) bits0 |= (1u << c);
        if (s1[c] > 0.5f) bits1 |= (1u << c);
    }
    const uint32_t curb = (cpv == 0) ? bits0 : bits1;
    const uint32_t oppb = (cpv == 0) ? bits1 : bits0;
    const uint32_t empb = (~(bits0 | bits1)) & MASK19;

    m_cur[lb][r + 1] = curb;
    m_opp[lb][r + 1] = oppb;
    m_emp[lb][r + 1] = empb;
    if (r == 0) {
        m_cur [lb][0] = 0u; m_cur [lb][20] = 0u;
        m_opp [lb][0] = 0u; m_opp [lb][20] = 0u;
        m_emp [lb][0] = 0u; m_emp [lb][20] = 0u;
        m_weak[lb][0] = 0u; m_weak[lb][20] = 0u;
    }
    __syncthreads();

    // ---------- Phase 2: weak = opp stone with exactly one opp neighbor ----------
    {
        const uint32_t ou = m_opp[lb][r];        // row above
        const uint32_t od = m_opp[lb][r + 2];    // row below
        const uint32_t ol = (oppb << 1) & MASK19; // left neighbor bit
        const uint32_t orr = oppb >> 1;           // right neighbor bit
        const uint32_t par = ou ^ od ^ ol ^ orr;                          // odd count (1 or 3)
        const uint32_t ge2 = (ou & od) | (ol & orr) | ((ou | od) & (ol | orr)); // >= 2 set
        m_weak[lb][r + 1] = oppb & par & ~ge2;   // exactly one
    }
    __syncthreads();

    // ---------- Phase 3: legal / cur_lib / outputs ----------
    const uint32_t weak = m_weak[lb][r + 1];

    const uint32_t eu = m_emp[lb][r],  ed = m_emp[lb][r + 2];
    const uint32_t nbr_emp  = eu | ed | ((empb << 1) & MASK19) | (empb >> 1);
    const uint32_t wu = m_weak[lb][r], wd = m_weak[lb][r + 2];
    const uint32_t nbr_weak = wu | wd | ((weak << 1) & MASK19) | (weak >> 1);

    uint32_t legal = empb & (nbr_emp | nbr_weak);

    // Ko point: clear legal bit at (rr, cc) when ko row >= 0 (rows/cols clipped).
    {
        const int kr = ko_points[2 * b];
        const int kc = ko_points[2 * b + 1];
        if (kr >= 0) {
            const int rr = kr > (HH - 1) ? (HH - 1) : kr;   // kr >= 0 already
            int cc = kc < 0 ? 0 : kc;
            cc = cc > (HH - 1) ? (HH - 1) : cc;
            if (rr == r) legal &= ~(1u << cc);
        }
    }

    // cur-neighbor rows for the liberty count
    const uint32_t cu  = m_cur[lb][r];
    const uint32_t cd  = m_cur[lb][r + 2];
    const uint32_t cl  = (curb << 1) & MASK19;
    const uint32_t crr = curb >> 1;

    if (active) {
        float* o = out + (size_t)b * (5 * CELLS) + r * HH;
        const float turn = (float)cpv;
#pragma unroll
        for (int c = 0; c < HH; ++c) {
            o[c]             = (float)((curb  >> c) & 1u);
            o[CELLS + c]     = (float)((oppb  >> c) & 1u);
            o[2 * CELLS + c] = (float)((legal >> c) & 1u);
            const uint32_t cnt = ((cu  >> c) & 1u) + ((cd  >> c) & 1u) +
                                 ((cl  >> c) & 1u) + ((crr >> c) & 1u);
            o[3 * CELLS + c] = ((empb >> c) & 1u) ? (float)cnt : 0.0f;
            o[4 * CELLS + c] = turn;
        }
    }
}

extern "C" void kernel_launch(void* const* d_in, const int* in_sizes, int n_in,
                              void* d_out, int out_size)
{
    const float* stones     = (const float*)d_in[0];
    const int*   cur_player = (const int*)  d_in[1];
    const int*   ko_points  = (const int*)  d_in[2];
    float*       out        = (float*)      d_out;

    const int B = in_sizes[1];                 // current_player has B elements
    const int grid = (B + BPB - 1) / BPB;
    go_feat_kernel<<<grid, NTHREADS>>>(stones, cur_player, ko_points, out, B);
}

// round 2
// speedup vs baseline: 4.1109x; 4.1109x over previous
#include <cuda_runtime.h>
#include <cstdint>

#define HH 19
#define CELLS 361
#define MASK19 0x7FFFFu
#define BPB 4                         // boards per block
#define NT 160                        // 5 warps
#define IN_WORDS (BPB * 722 / 4)      // 722 packed uint32 (input bytes /4)
#define OUT_VEC4 (BPB * 1805 / 4)     // 1805 float4 per block

__global__ __launch_bounds__(NT)
void go_feat_kernel(const float* __restrict__ stones,
                    const int*   __restrict__ cur_player,
                    const int*   __restrict__ ko_points,
                    float*       __restrict__ out,
                    int B)
{
    // 0/1 bytes for each input cell of the block's BPB boards (2 channels)
    __shared__ uint32_t s_in[IN_WORDS];                 // 2888 B
    // padded row bitmasks: rows [1..19] real, rows 0/20 zero
    __shared__ uint32_t s_cur [BPB][21];
    __shared__ uint32_t s_opp [BPB][21];
    __shared__ uint32_t s_emp [BPB][21];
    __shared__ uint32_t s_weak[BPB][21];                // 1344 B
    __shared__ int      s_cp[BPB];
    __shared__ __align__(16) float s_out[BPB * 5 * CELLS];  // 28880 B

    const int t     = threadIdx.x;
    const int bbase = blockIdx.x * BPB;
    const int rb    = (B - bbase) < BPB ? (B - bbase) : BPB;   // boards in this block
    const bool full = (rb == BPB);

    // ---------------- Phase 0: coalesced input load -> 0/1 bytes ----------------
    if (full) {
        const float4* src = (const float4*)(stones + (size_t)bbase * 722);
        for (int i = t; i < IN_WORDS; i += NT) {
            float4 v = src[i];
            uint32_t p = (v.x > 0.5f ? 1u : 0u)
                       | (v.y > 0.5f ? 1u : 0u) << 8
                       | (v.z > 0.5f ? 1u : 0u) << 16
                       | (v.w > 0.5f ? 1u : 0u) << 24;
            s_in[i] = p;
        }
    } else {
        const float* src = stones + (size_t)bbase * 722;
        uint8_t* sb = (uint8_t*)s_in;
        for (int i = t; i < rb * 722; i += NT)
            sb[i] = src[i] > 0.5f ? 1u : 0u;
    }
    __syncthreads();

    // ---------------- Phase 1: pack bytes -> 19-bit row masks ----------------
    if (t < BPB * 2 * HH) {                      // 152 threads
        const int p  = t / HH;                   // plane 0..7  (board*2 + channel)
        const int r  = t % HH;
        const int lb = p >> 1;
        const int ch = p & 1;
        if (lb < rb) {
            const uint8_t* row = ((const uint8_t*)s_in) + p * CELLS + r * HH;
            uint32_t bits = 0u;
#pragma unroll
            for (int c = 0; c < HH; ++c)
                bits |= (uint32_t)row[c] << c;
            const int cp = cur_player[bbase + lb];
            // cur = stones[cp], opp = stones[1-cp]
            if (ch == cp) s_cur[lb][r + 1] = bits;
            else          s_opp[lb][r + 1] = bits;
            if (r == 0 && ch == 0) {
                s_cp[lb] = cp;
                s_cur [lb][0] = 0u; s_cur [lb][20] = 0u;
                s_opp [lb][0] = 0u; s_opp [lb][20] = 0u;
                s_emp [lb][0] = 0u; s_emp [lb][20] = 0u;
                s_weak[lb][0] = 0u; s_weak[lb][20] = 0u;
            }
        }
    }
    __syncthreads();

    // ---------------- Phase 2: weak (opp w/ exactly 1 opp nbr) + empty ----------
    if (t < BPB * HH) {                          // 76 threads
        const int lb = t / HH, r = t % HH;
        if (lb < rb) {
            const uint32_t o   = s_opp[lb][r + 1];
            const uint32_t ou  = s_opp[lb][r];
            const uint32_t od  = s_opp[lb][r + 2];
            const uint32_t ol  = (o << 1) & MASK19;
            const uint32_t orr = o >> 1;
            const uint32_t par = ou ^ od ^ ol ^ orr;
            const uint32_t ge2 = (ou & od) | (ol & orr) | ((ou | od) & (ol | orr));
            s_weak[lb][r + 1] = o & par & ~ge2;
            s_emp [lb][r + 1] = (~(s_cur[lb][r + 1] | o)) & MASK19;
        }
    }
    __syncthreads();

    // ---------------- Phase 3: legal / liberties -> staged output ----------------
    if (t < BPB * HH) {
        const int lb = t / HH, r = t % HH;
        if (lb < rb) {
            const int b = bbase + lb;
            const uint32_t curb = s_cur[lb][r + 1];
            const uint32_t oppb = s_opp[lb][r + 1];
            const uint32_t empb = s_emp[lb][r + 1];

            const uint32_t eu = s_emp [lb][r], ed = s_emp [lb][r + 2];
            const uint32_t wk = s_weak[lb][r + 1];
            const uint32_t wu = s_weak[lb][r], wd = s_weak[lb][r + 2];
            const uint32_t nbr = eu | ed | ((empb << 1) & MASK19) | (empb >> 1)
                               | wu | wd | ((wk  << 1) & MASK19) | (wk  >> 1);
            uint32_t legal = empb & nbr;

            const int kr = ko_points[2 * b];
            const int kc = ko_points[2 * b + 1];
            if (kr >= 0) {
                const int rr = kr > (HH - 1) ? (HH - 1) : kr;
                int cc = kc < 0 ? 0 : kc;
                cc = cc > (HH - 1) ? (HH - 1) : cc;
                if (rr == r) legal &= ~(1u << cc);
            }

            const uint32_t cu  = s_cur[lb][r];
            const uint32_t cd  = s_cur[lb][r + 2];
            const uint32_t cl  = (curb << 1) & MASK19;
            const uint32_t crr = curb >> 1;

            float* o = s_out + lb * 5 * CELLS + r * HH;
            const float turn = (float)s_cp[lb];
#pragma unroll
            for (int c = 0; c < HH; ++c) {
                o[c]             = (float)((curb  >> c) & 1u);
                o[CELLS + c]     = (float)((oppb  >> c) & 1u);
                o[2 * CELLS + c] = (float)((legal >> c) & 1u);
                const uint32_t cnt = ((cu  >> c) & 1u) + ((cd  >> c) & 1u)
                                   + ((cl  >> c) & 1u) + ((crr >> c) & 1u);
                o[3 * CELLS + c] = ((empb >> c) & 1u) ? (float)cnt : 0.0f;
                o[4 * CELLS + c] = turn;
            }
        }
    }
    __syncthreads();

    // ---------------- Phase 4: coalesced bulk store ----------------
    if (full) {
        float4* dst = (float4*)(out + (size_t)bbase * 5 * CELLS);
        const float4* so4 = (const float4*)s_out;
        for (int i = t; i < OUT_VEC4; i += NT)
            dst[i] = so4[i];
    } else {
        float* dst = out + (size_t)bbase * 5 * CELLS;
        for (int i = t; i < rb * 5 * CELLS; i += NT)
            dst[i] = s_out[i];
    }
}

extern "C" void kernel_launch(void* const* d_in, const int* in_sizes, int n_in,
                              void* d_out, int out_size)
{
    const float* stones     = (const float*)d_in[0];
    const int*   cur_player = (const int*)  d_in[1];
    const int*   ko_points  = (const int*)  d_in[2];
    float*       out        = (float*)      d_out;

    const int B = in_sizes[1];               // current_player has B elements
    const int grid = (B + BPB - 1) / BPB;
    go_feat_kernel<<<grid, NT>>>(stones, cur_player, ko_points, out, B);
}

// round 3
// speedup vs baseline: 4.5744x; 1.1128x over previous
#include <cuda_runtime.h>
#include <cstdint>

#define HH 19
#define CELLS 361
#define MASK19 0x7FFFFu
#define BPB 4                          // boards per block
#define NT 384                         // 12 warps
#define IN_WORDS (BPB * 722 / 4)       // 722 packed uint32 (input bytes /4)
#define OUT_WORDS (BPB * 5 * CELLS)    // 7220 uint32 = 1805 uint4

#define ONEF  0x3F800000u
#define TWOF  0x40000000u
#define FOURF 0x40800000u

// bit c of m, as float-1.0 bit pattern masked by K
__device__ __forceinline__ uint32_t bitf(uint32_t m, int c, uint32_t K) {
    return (uint32_t)(((int32_t)(m << (31 - c))) >> 31) & K;
}

__global__ __launch_bounds__(NT, 4)
void go_feat_kernel(const float* __restrict__ stones,
                    const int*   __restrict__ cur_player,
                    const int*   __restrict__ ko_points,
                    float*       __restrict__ out,
                    int B)
{
    __shared__ uint32_t s_in[IN_WORDS];                    // 2888 B packed 0/1 bytes
    __shared__ uint32_t s_cur [BPB][21];                   // padded row masks
    __shared__ uint32_t s_opp [BPB][21];
    __shared__ uint32_t s_emp [BPB][21];
    __shared__ uint32_t s_weak[BPB][21];
    __shared__ int      s_cp[BPB];
    __shared__ __align__(16) uint32_t s_out[OUT_WORDS];    // 28880 B

    const int t     = threadIdx.x;
    const int bbase = blockIdx.x * BPB;
    const int rb    = (B - bbase) < BPB ? (B - bbase) : BPB;
    const bool full = (rb == BPB);

    // ---------------- Phase 0: coalesced input load -> 0/1 bytes ----------------
    if (full) {
        const float4* src = (const float4*)(stones + (size_t)bbase * 722);
        for (int i = t; i < IN_WORDS; i += NT) {
            float4 v = src[i];
            uint32_t p = (v.x > 0.5f ? 1u : 0u)
                       | (v.y > 0.5f ? 1u : 0u) << 8
                       | (v.z > 0.5f ? 1u : 0u) << 16
                       | (v.w > 0.5f ? 1u : 0u) << 24;
            s_in[i] = p;
        }
    } else {
        const float* src = stones + (size_t)bbase * 722;
        uint8_t* sb = (uint8_t*)s_in;
        for (int i = t; i < rb * 722; i += NT)
            sb[i] = src[i] > 0.5f ? 1u : 0u;
    }
    __syncthreads();

    // ---------------- Phase 1: pack bytes -> 19-bit row masks ----------------
    if (t < BPB * 2 * HH) {                      // 152 threads: plane-row
        const int p  = t / HH;                   // plane 0..7 = lb*2 + ch
        const int r  = t % HH;
        const int lb = p >> 1;
        const int ch = p & 1;
        if (lb < rb) {
            const uint8_t* row = ((const uint8_t*)s_in) + p * CELLS + r * HH;
            uint32_t bits = 0u;
#pragma unroll
            for (int c = 0; c < HH; ++c)
                bits |= (uint32_t)row[c] << c;
            const int cp = cur_player[bbase + lb];
            if (ch == cp) s_cur[lb][r + 1] = bits;
            else          s_opp[lb][r + 1] = bits;
            if (r == 0 && ch == 0) {
                s_cp[lb] = cp;
                s_cur [lb][0] = 0u; s_cur [lb][20] = 0u;
                s_opp [lb][0] = 0u; s_opp [lb][20] = 0u;
                s_emp [lb][0] = 0u; s_emp [lb][20] = 0u;
                s_weak[lb][0] = 0u; s_weak[lb][20] = 0u;
            }
        }
    }
    __syncthreads();

    // ---------------- Phase 2: weak (opp with exactly 1 opp nbr) + empty --------
    if (t < BPB * HH) {                          // 76 threads
        const int lb = t / HH, r = t % HH;
        if (lb < rb) {
            const uint32_t o   = s_opp[lb][r + 1];
            const uint32_t ou  = s_opp[lb][r];
            const uint32_t od  = s_opp[lb][r + 2];
            const uint32_t ol  = (o << 1) & MASK19;
            const uint32_t orr = o >> 1;
            const uint32_t par = ou ^ od ^ ol ^ orr;
            const uint32_t ge2 = (ou & od) | (ol & orr) | ((ou | od) & (ol | orr));
            s_weak[lb][r + 1] = o & par & ~ge2;
            s_emp [lb][r + 1] = (~(s_cur[lb][r + 1] | o)) & MASK19;
        }
    }
    __syncthreads();

    // ---------------- Phase 3: one thread per (channel, board, row) -------------
    if (t < 5 * BPB * HH) {                      // 380 threads
        const int ch = t / (BPB * HH);           // 0..4
        const int w  = t % (BPB * HH);
        const int lb = w / HH;
        const int r  = w % HH;
        if (lb < rb) {
            uint32_t* o = s_out + lb * (5 * CELLS) + ch * CELLS + r * HH;

            if (ch == 3) {
                // cur_lib = (#cur neighbors) * empty  — carry-save bit planes
                const uint32_t curb = s_cur[lb][r + 1];
                const uint32_t cu   = s_cur[lb][r];
                const uint32_t cd   = s_cur[lb][r + 2];
                const uint32_t cl   = (curb << 1) & MASK19;
                const uint32_t crr  = curb >> 1;
                const uint32_t empb = s_emp[lb][r + 1];

                const uint32_t sab = cu ^ cd,  cab = cu & cd;
                const uint32_t scd = cl ^ crr, ccd = cl & crr;
                const uint32_t k   = sab & scd;
                uint32_t b0 = (sab ^ scd)     & empb;   // ones
                uint32_t b1 = (cab ^ ccd ^ k) & empb;   // twos
                uint32_t b2 = (cab & ccd)     & empb;   // fours
#pragma unroll
                for (int c = 0; c < HH; ++c) {
                    float f = __uint_as_float(bitf(b0, c, ONEF))
                            + __uint_as_float(bitf(b1, c, TWOF))
                            + __uint_as_float(bitf(b2, c, FOURF));
                    o[c] = __float_as_uint(f);
                }
            } else {
                uint32_t m;
                if (ch == 0)      m = s_cur[lb][r + 1];
                else if (ch == 1) m = s_opp[lb][r + 1];
                else if (ch == 4) m = s_cp[lb] ? MASK19 : 0u;
                else {
                    // legal = empty & (nbr(empty) | nbr(weak)), minus ko point
                    const uint32_t empb = s_emp[lb][r + 1];
                    const uint32_t eu = s_emp [lb][r], ed = s_emp [lb][r + 2];
                    const uint32_t wk = s_weak[lb][r + 1];
                    const uint32_t wu = s_weak[lb][r], wd = s_weak[lb][r + 2];
                    const uint32_t nbr = eu | ed | ((empb << 1) & MASK19) | (empb >> 1)
                                       | wu | wd | ((wk  << 1) & MASK19) | (wk  >> 1);
                    m = empb & nbr;
                    const int b  = bbase + lb;
                    const int kr = ko_points[2 * b];
                    const int kc = ko_points[2 * b + 1];
                    if (kr >= 0) {
                        const int rr = kr > (HH - 1) ? (HH - 1) : kr;
                        int cc = kc < 0 ? 0 : kc;
                        cc = cc > (HH - 1) ? (HH - 1) : cc;
                        if (rr == r) m &= ~(1u << cc);
                    }
                }
#pragma unroll
                for (int c = 0; c < HH; ++c)
                    o[c] = bitf(m, c, ONEF);
            }
        }
    }
    __syncthreads();

    // ---------------- Phase 4: coalesced bulk store ----------------
    if (full) {
        uint4* dst = (uint4*)(out + (size_t)bbase * (5 * CELLS));
        const uint4* so4 = (const uint4*)s_out;
        for (int i = t; i < OUT_WORDS / 4; i += NT)
            dst[i] = so4[i];
    } else {
        uint32_t* dst = (uint32_t*)(out + (size_t)bbase * (5 * CELLS));
        for (int i = t; i < rb * 5 * CELLS; i += NT)
            dst[i] = s_out[i];
    }
}

extern "C" void kernel_launch(void* const* d_in, const int* in_sizes, int n_in,
                              void* d_out, int out_size)
{
    const float* stones     = (const float*)d_in[0];
    const int*   cur_player = (const int*)  d_in[1];
    const int*   ko_points  = (const int*)  d_in[2];
    float*       out        = (float*)      d_out;

    const int B = in_sizes[1];               // current_player has B elements
    const int grid = (B + BPB - 1) / BPB;
    go_feat_kernel<<<grid, NT>>>(stones, cur_player, ko_points, out, B);
}